// round 7
// baseline (speedup 1.0000x reference)
#include <cuda_runtime.h>
#include <cuda_bf16.h>
#include <math.h>

// Problem constants
#define BB 1024   // batch
#define II 256    // in features
#define OO 256    // out features
#define KK 128    // knots

// Spline-kernel tiling
#define OT 32               // o per CTA (one per lane)
#define NICHUNK 16          // i-chunks in grid
#define IPC (II / NICHUNK)  // 16 i per chunk
#define PSTR 129            // ptile row stride in float2 (odd -> conflict-free gathers)
#define BH 512              // b's per half
#define BPW 16              // b's per warp per half (acc[16])

// Dynamic smem layout (bytes)
#define PTILE_BYTES (OT * PSTR * 8)          // 33024
#define MTILE_OFF   PTILE_BYTES
#define MTILE_BYTES (BH * 16)                // 8192 (one half's meta)
#define WSTILE_OFF  (MTILE_OFF + MTILE_BYTES)
#define WSTILE_BYTES (OT * 17 * 8)           // 4352
#define SMEM_TOTAL  (WSTILE_OFF + WSTILE_BYTES)

// Scratch: meta[i][b] = {frac, (l*8) byte-offset as bits, silu, unused}
__device__ float4 g_meta[II * BB];   // 4 MB

// ---------------------------------------------------------------------------
// Kernel 1: activation/knot prep (transposed meta write) + out=bias init.
// grid (II/32, BB/32), block (32,32) -> 262144 threads == BB*OO elements.
// ---------------------------------------------------------------------------
__global__ void kan_prep(const float* __restrict__ x,
                         const float* __restrict__ bias,
                         float* __restrict__ out) {
    __shared__ float4 sm[32][33];
    int i = blockIdx.x * 32 + threadIdx.x;
    int b = blockIdx.y * 32 + threadIdx.y;

    float xv = x[b * II + i];
    float p = tanhf(xv);                         // accurate tanh (63.5x error amplification downstream)
    float sig = 1.0f / (1.0f + __expf(-p));
    float silu = p * sig;
    float c = fminf(fmaxf(p, -1.0f), 1.0f);
    float scaled = (c + 1.0f) * 63.5f;           // (c - DMIN)/step, step = 2/127
    int l = (int)scaled;
    if (l > 126) l = 126;                        // pair entry l -> l=126,f=1 gives c[127] exactly
    float frac = scaled - (float)l;

    sm[threadIdx.y][threadIdx.x] = make_float4(frac, __int_as_float(l * 8), silu, 0.0f);

    // out initialization (out arrives poisoned; spline kernel atomically adds)
    int gid = (blockIdx.y * gridDim.x + blockIdx.x) * 1024 + threadIdx.y * 32 + threadIdx.x;
    out[gid] = bias[gid & (OO - 1)];

    __syncthreads();

    int i2 = blockIdx.x * 32 + threadIdx.y;
    int b2 = blockIdx.y * 32 + threadIdx.x;
    g_meta[i2 * BB + b2] = sm[threadIdx.x][threadIdx.y];  // coalesced over b2
}

// ---------------------------------------------------------------------------
// Kernel 2: spline gather + base GEMM.
// grid = (NICHUNK, 1, OO/OT) = 128 CTAs (1/SM), block = 1024 (32 warps).
// Fused loop t = 0..31: half h = t>>4 (b-range [512h,512h+512)), ii = t&15.
// Warp w owns b in [512h + 16w, +16)  ->  acc[16], regs fit under the 64 cap.
// Depth-2 register prefetch (A/B buffers) hides coeff/meta L2 latency.
// ---------------------------------------------------------------------------
__global__ __launch_bounds__(1024, 1)
void kan_spline(const float* __restrict__ coeff,   // [O][I][K]
                const float* __restrict__ scale,   // [O][I]
                const float* __restrict__ bw,      // [O][I]
                float* __restrict__ out) {         // [B][O]
    extern __shared__ char smem_raw[];
    float2* ptile  = (float2*)smem_raw;                       // [OT][PSTR] {c[k], c[k+1]-c[k]}
    float4* mtile  = (float4*)(smem_raw + MTILE_OFF);         // [BH] meta of current half
    float2* wstile = (float2*)(smem_raw + WSTILE_OFF);        // [OT][17] {w, sc}

    const int tid  = threadIdx.x;
    const int lane = tid & 31;
    const int warp = tid >> 5;
    const int o0 = blockIdx.z * OT;
    const int i0 = blockIdx.x * IPC;

    // preload {base-weight, spline-scale} tile: [o][ii] (shared by both halves)
    if (tid < OT * IPC) {
        int o  = tid >> 4;      // 0..31
        int ii = tid & 15;      // 0..15
        size_t gi = (size_t)(o0 + o) * II + i0 + ii;
        wstile[o * 17 + ii] = make_float2(bw[gi], scale[gi]);
    }

    float acc[BPW];
#pragma unroll
    for (int j = 0; j < BPW; j++) acc[j] = 0.0f;

    const char* myrow = (const char*)(ptile + lane * PSTR);
    const float4* crow = (const float4*)(coeff + ((size_t)(o0 + warp) * II + i0) * KK);

    // prefetch t=0 into A, t=1 into B  (t: h = t>>4, ii = t&15; coeff row advances by KK floats per ii)
    float4 cregA = crow[lane];                 // (h0, ii0)
    float4 cregB = crow[32 + lane];            // (h0, ii1)  [lane index advances by KK/4=32 float4s]
    float4 mregA, mregB;
    if (tid < BH) {
        mregA = g_meta[(size_t)i0 * BB + tid];
        mregB = g_meta[(size_t)(i0 + 1) * BB + tid];
    }

    for (int t = 0; t < 32; t++) {
        const int ii = t & 15;
        const bool useA = !(t & 1);
        float4 creg = useA ? cregA : cregB;

        __syncthreads();   // previous tile's readers done

        // build pair-difference tile {c[k], c[k+1]-c[k]}
        {
            float nxt = __shfl_down_sync(0xffffffffu, creg.x, 1);
            float2* prow = ptile + warp * PSTR + lane * 4;
            prow[0] = make_float2(creg.x, creg.y - creg.x);
            prow[1] = make_float2(creg.y, creg.z - creg.y);
            prow[2] = make_float2(creg.z, creg.w - creg.z);
            prow[3] = make_float2(creg.w, nxt - creg.w);   // k=127 diff unused (l<=126)
            if (tid < BH) mtile[tid] = useA ? mregA : mregB;
        }
        __syncthreads();   // tile ready

        // prefetch t+2 into the buffer just freed
        const int pf = t + 2;
        if (pf < 32) {
            const int pii = pf & 15;
            const int ph  = pf >> 4;
            float4 c = crow[pii * (KK / 4) + lane];
            if (useA) cregA = c; else cregB = c;
            if (tid < BH) {
                float4 m = g_meta[(size_t)(i0 + pii) * BB + ph * BH + tid];
                if (useA) mregA = m; else mregB = m;
            }
        }

        float2 ws = wstile[lane * 17 + ii];   // {w[o,i], sc[o,i]}

#pragma unroll
        for (int bb = 0; bb < BPW; bb++) {
            float4 m = mtile[warp * BPW + bb];                          // broadcast
            float2 cd = *(const float2*)(myrow + __float_as_int(m.y));  // conflict-free LDS.64
            float v = fmaf(m.x, cd.y, cd.x);                            // lerp: cl + f*(cr-cl)
            acc[bb] = fmaf(ws.y, v, fmaf(m.z, ws.x, acc[bb]));          // + sc*spline + silu*W
        }

        if (ii == 15) {   // flush this half's accumulators
            const int h = t >> 4;
            float* op = out + (size_t)(h * BH + warp * BPW) * OO + o0 + lane;
#pragma unroll
            for (int bb = 0; bb < BPW; bb++) {
                atomicAdd(op + (size_t)bb * OO, acc[bb]);
                acc[bb] = 0.0f;
            }
        }
    }
}

// ---------------------------------------------------------------------------
// Launch
// ---------------------------------------------------------------------------
extern "C" void kernel_launch(void* const* d_in, const int* in_sizes, int n_in,
                              void* d_out, int out_size) {
    const float* x     = (const float*)d_in[0];  // [B][I]
    const float* bw    = (const float*)d_in[1];  // [O][I]
    const float* coeff = (const float*)d_in[2];  // [O][I][K]
    const float* scale = (const float*)d_in[3];  // [O][I]
    const float* bias  = (const float*)d_in[4];  // [O]
    float* out = (float*)d_out;                  // [B][O]

    static bool attr_set = false;
    if (!attr_set) {
        cudaFuncSetAttribute(kan_spline, cudaFuncAttributeMaxDynamicSharedMemorySize, SMEM_TOTAL);
        attr_set = true;
    }

    kan_prep<<<dim3(II / 32, BB / 32), dim3(32, 32)>>>(x, bias, out);
    kan_spline<<<dim3(NICHUNK, 1, OO / OT), 1024, SMEM_TOTAL>>>(coeff, scale, bw, out);
}